// round 15
// baseline (speedup 1.0000x reference)
#include <cuda_runtime.h>
#include <cuda_fp16.h>
#include <math.h>
#include <stdint.h>

// ---------------- problem constants ----------------
#define S_TOK   4096
#define CDIM    1024
#define EXP     64
#define TOPK    8
#define NGRP    8
#define EPG     8
#define TGRP    4
#define HDIM    512
#define HSHARED 2048
#define NROWS   (S_TOK * TOPK)   // 32768
#define MAX_TILES 320
#define SEL_BLK 128
#define SEL_NBLK (S_TOK / SEL_BLK)   // 32

// ---------------- scratch (static device globals) ----------------
struct TileDesc { int e; int row_start; int rows; };

__device__ int      g_cnt_part[SEL_NBLK * EXP];
__device__ int      g_cursor[EXP];
__device__ TileDesc g_tiles[MAX_TILES];
__device__ int      g_ntiles;
__device__ int      g_rowmap[NROWS];
__device__ int      g_topk_idx[NROWS];
__device__ float    g_topk_w[NROWS];
__device__ float    g_scores[(size_t)S_TOK * EXP];

__device__ __half   g_hbuf[(size_t)NROWS * HDIM];       // routed h (post-swiglu)
__device__ __half   g_sh_h[(size_t)S_TOK * HSHARED];    // shared h (post-swiglu)
__device__ __half   g_x_r[(size_t)S_TOK * CDIM];

// fp16 weight copies (native [K][N] layouts preserved)
__device__ __half   g_w_gate[(size_t)EXP * CDIM * HDIM];
__device__ __half   g_w_up[(size_t)EXP * CDIM * HDIM];
__device__ __half   g_w_down[(size_t)EXP * HDIM * CDIM];
__device__ __half   g_w_shg[(size_t)CDIM * HSHARED];
__device__ __half   g_w_shu[(size_t)CDIM * HSHARED];
__device__ __half   g_w_shd[(size_t)HSHARED * CDIM];

// ---------------- helpers ----------------
__device__ __forceinline__ void mma_f16(float* c, const uint32_t* a, const uint32_t* b) {
    asm volatile(
        "mma.sync.aligned.m16n8k16.row.col.f32.f16.f16.f32 "
        "{%0,%1,%2,%3}, {%4,%5,%6,%7}, {%8,%9}, {%0,%1,%2,%3};"
        : "+f"(c[0]), "+f"(c[1]), "+f"(c[2]), "+f"(c[3])
        : "r"(a[0]), "r"(a[1]), "r"(a[2]), "r"(a[3]), "r"(b[0]), "r"(b[1]));
}
__device__ __forceinline__ void ldmatrix_x4(uint32_t* r, uint32_t addr) {
    asm volatile("ldmatrix.sync.aligned.m8n8.x4.shared.b16 {%0,%1,%2,%3}, [%4];"
                 : "=r"(r[0]), "=r"(r[1]), "=r"(r[2]), "=r"(r[3]) : "r"(addr));
}
__device__ __forceinline__ void ldmatrix_x4_trans(uint32_t* r, uint32_t addr) {
    asm volatile("ldmatrix.sync.aligned.m8n8.x4.trans.shared.b16 {%0,%1,%2,%3}, [%4];"
                 : "=r"(r[0]), "=r"(r[1]), "=r"(r[2]), "=r"(r[3]) : "r"(addr));
}
__device__ __forceinline__ void cp_async16(uint32_t dst, const void* src, int srcbytes) {
    asm volatile("cp.async.cg.shared.global [%0], [%1], 16, %2;"
                 :: "r"(dst), "l"(src), "r"(srcbytes));
}
__device__ __forceinline__ void red_add_v2(float* ptr, float a, float b) {
    asm volatile("red.global.add.v2.f32 [%0], {%1, %2};"
                 :: "l"(ptr), "f"(a), "f"(b) : "memory");
}

// ---------------- prep: f32 -> f16 convert copies ----------------
__global__ void half_copy(const float4* __restrict__ src, __half2* __restrict__ dst,
                          long long n4) {
    long long i = (long long)blockIdx.x * blockDim.x + threadIdx.x;
    if (i >= n4) return;
    float4 v = src[i];
    dst[i * 2 + 0] = __floats2half2_rn(v.x, v.y);
    dst[i * 2 + 1] = __floats2half2_rn(v.z, v.w);
}

#define EW_N4_SHIFT 23
__global__ void half_copy3(const float4* __restrict__ s0, const float4* __restrict__ s1,
                           const float4* __restrict__ s2,
                           __half2* __restrict__ d0, __half2* __restrict__ d1,
                           __half2* __restrict__ d2) {
    long long i = (long long)blockIdx.x * blockDim.x + threadIdx.x;
    int sel = (int)(i >> EW_N4_SHIFT);
    long long idx = i & ((1LL << EW_N4_SHIFT) - 1);
    const float4* s = (sel == 0) ? s0 : (sel == 1) ? s1 : s2;
    __half2* d = (sel == 0) ? d0 : (sel == 1) ? d1 : d2;
    float4 v = s[idx];
    d[idx * 2 + 0] = __floats2half2_rn(v.x, v.y);
    d[idx * 2 + 1] = __floats2half2_rn(v.z, v.w);
}

// ---------------- routing ----------------
#define SCORE_TOK 16
#define XS_STRIDE 1028
__global__ void __launch_bounds__(256) score_kernel(
    const float* __restrict__ x, const float* __restrict__ rw,
    float* __restrict__ scores) {
    extern __shared__ float xs[];   // [SCORE_TOK][XS_STRIDE]
    int t0 = blockIdx.y * SCORE_TOK;
    int tid = threadIdx.x, lane = tid & 31, wid = tid >> 5;

    for (int idx = tid; idx < SCORE_TOK * 256; idx += 256) {
        int t = idx >> 8, j = idx & 255;
        *(float4*)&xs[t * XS_STRIDE + j * 4] =
            *(const float4*)(x + (size_t)(t0 + t) * CDIM + j * 4);
    }
    __syncthreads();

    int e0 = blockIdx.x * 16 + wid * 2;
    const float* w0 = rw + (size_t)e0 * CDIM;
    const float* w1 = rw + (size_t)(e0 + 1) * CDIM;
    float acc0[SCORE_TOK], acc1[SCORE_TOK];
    #pragma unroll
    for (int t = 0; t < SCORE_TOK; t++) { acc0[t] = 0.f; acc1[t] = 0.f; }

    #pragma unroll
    for (int i = 0; i < 8; i++) {
        int c = lane * 4 + i * 128;
        float4 a = *(const float4*)(w0 + c);
        float4 b = *(const float4*)(w1 + c);
        #pragma unroll
        for (int t = 0; t < SCORE_TOK; t++) {
            float4 xv = *(const float4*)&xs[t * XS_STRIDE + c];
            acc0[t] += a.x * xv.x + a.y * xv.y + a.z * xv.z + a.w * xv.w;
            acc1[t] += b.x * xv.x + b.y * xv.y + b.z * xv.z + b.w * xv.w;
        }
    }
    #pragma unroll
    for (int t = 0; t < SCORE_TOK; t++) {
        float s0 = acc0[t], s1 = acc1[t];
        #pragma unroll
        for (int o = 16; o > 0; o >>= 1) {
            s0 += __shfl_xor_sync(0xffffffffu, s0, o);
            s1 += __shfl_xor_sync(0xffffffffu, s1, o);
        }
        if (lane == 0) {
            scores[(size_t)(t0 + t) * EXP + e0]     = 1.f / (1.f + expf(-s0));
            scores[(size_t)(t0 + t) * EXP + e0 + 1] = 1.f / (1.f + expf(-s1));
        }
    }
}

__global__ void __launch_bounds__(SEL_BLK) select_kernel(
    const float* __restrict__ scores, const float* __restrict__ ebias) {
    __shared__ float sbs[SEL_BLK * 65];
    __shared__ float eb[EXP];
    __shared__ int cnt[EXP];
    int tid = threadIdx.x;
    if (tid < EXP) { cnt[tid] = 0; eb[tid] = ebias[tid]; }
    __syncthreads();

    int t = blockIdx.x * SEL_BLK + tid;
    float* sb = &sbs[tid * 65];
    const float* srow = scores + (size_t)t * EXP;
    for (int e = 0; e < EXP; e++) sb[e] = srow[e] + eb[e];

    float grp[NGRP];
    for (int g = 0; g < NGRP; g++) {
        float m1 = -1e30f, m2 = -1e30f;
        for (int j = 0; j < EPG; j++) {
            float v = sb[g * EPG + j];
            if (v > m1) { m2 = m1; m1 = v; }
            else if (v > m2) m2 = v;
        }
        grp[g] = m1 + m2;
    }
    bool gsel[NGRP] = {};
    for (int it = 0; it < TGRP; it++) {
        float best = -1e30f; int bi = 0;
        for (int g = 0; g < NGRP; g++)
            if (!gsel[g] && grp[g] > best) { best = grp[g]; bi = g; }
        gsel[bi] = true;
    }
    bool eused[EXP] = {};
    int idx[TOPK]; float wv[TOPK]; float wsum = 0.f;
    for (int it = 0; it < TOPK; it++) {
        float best = -1e30f; int bi = 0;
        for (int e = 0; e < EXP; e++)
            if (gsel[e / EPG] && !eused[e] && sb[e] > best) { best = sb[e]; bi = e; }
        eused[bi] = true; idx[it] = bi;
        float s = srow[bi];
        wv[it] = s; wsum += s;
    }
    float inv = 1.f / (wsum + 1e-20f);
    for (int it = 0; it < TOPK; it++) {
        g_topk_idx[t * TOPK + it] = idx[it];
        g_topk_w[t * TOPK + it]   = wv[it] * inv;
        atomicAdd(&cnt[idx[it]], 1);
    }
    __syncthreads();
    if (tid < EXP) g_cnt_part[blockIdx.x * EXP + tid] = cnt[tid];
}

__global__ void setup_kernel() {
    __shared__ int s[EXP];
    __shared__ int s2[EXP];
    int t = threadIdx.x;
    int c = 0;
    for (int b = 0; b < SEL_NBLK; b++) c += g_cnt_part[b * EXP + t];
    int nt_e = (c + 127) >> 7;
    s[t] = c; s2[t] = nt_e;
    __syncthreads();
    for (int off = 1; off < EXP; off <<= 1) {
        int v = (t >= off) ? s[t - off] : 0;
        int v2 = (t >= off) ? s2[t - off] : 0;
        __syncthreads();
        s[t] += v; s2[t] += v2;
        __syncthreads();
    }
    int off_e = s[t] - c;
    int toff_e = s2[t] - nt_e;
    g_cursor[t] = off_e;
    if (t == EXP - 1) g_ntiles = s2[t];
    for (int r = 0, k = 0; r < c; r += 128, k++) {
        g_tiles[toff_e + k].e = t;
        g_tiles[toff_e + k].row_start = off_e + r;
        g_tiles[toff_e + k].rows = min(128, c - r);
    }
}

__global__ void assign_kernel() {
    int d = blockIdx.x * blockDim.x + threadIdx.x;
    if (d >= NROWS) return;
    int e = g_topk_idx[d];
    int pos = atomicAdd(&g_cursor[e], 1);
    g_rowmap[pos] = d;
}

// ---------------- GEMM tiling constants ----------------
#define GEMM_THREADS 128
#define STAGES 5
#define A_STRIDE_H 40
#define B_STRIDE_H 136
#define A_SZ_H (128 * A_STRIDE_H)           // 5120 halfs
#define B_SZ_H (32 * B_STRIDE_H)            // 4352 halfs
#define PIPE_H (STAGES * (A_SZ_H + B_SZ_H)) // 47360 halfs = 94720 B
#define GEMM_SMEM_BYTES (PIPE_H * 2 + 512)  // + tokmap

// ================= fused gate|up GEMM + in-register SwiGLU =================
template <bool GROUPED, bool INDIRECT>
__global__ void __launch_bounds__(GEMM_THREADS, 2) gu_gemm(
    const __half* __restrict__ A, const __half* __restrict__ Bg,
    const __half* __restrict__ Bu, __half* __restrict__ Hout,
    int Kd, int Nh, long long strideB) {
    extern __shared__ __half smem_h[];
    int* tokmap = (int*)(smem_h + PIPE_H);

    int row_start, rows, e;
    if (GROUPED) {
        if ((int)blockIdx.y >= g_ntiles) return;
        TileDesc td = g_tiles[blockIdx.y];
        e = td.e; row_start = td.row_start; rows = td.rows;
    } else {
        e = 0; row_start = blockIdx.y * 128; rows = 128;
    }
    int h0 = blockIdx.x * 64;
    const __half* Bgp = Bg + (long long)e * strideB + h0;
    const __half* Bup = Bu + (long long)e * strideB + h0;
    const __half* Aptr = A + (long long)row_start * Kd;

    int tid = threadIdx.x;
    int lane = tid & 31, wid = tid >> 5;
    int g = lane >> 2, tig = lane & 3;
    int wmb = (wid >> 1) * 64;
    int wnb = (wid & 1) * 64;

    if (INDIRECT) {
        tokmap[tid] = (tid < rows) ? (g_rowmap[row_start + tid] / TOPK) : -1;
        __syncthreads();
    }

    uint32_t sb = (uint32_t)__cvta_generic_to_shared(smem_h);

    float acc[4][8][4];
    #pragma unroll
    for (int mi = 0; mi < 4; mi++)
        #pragma unroll
        for (int ni = 0; ni < 8; ni++)
            #pragma unroll
            for (int q = 0; q < 4; q++) acc[mi][ni][q] = 0.f;

    const int T = Kd >> 5;

    auto issue = [&](int stage, int it) {
        int kk = it * 32;
        uint32_t abase = sb + (uint32_t)(stage * A_SZ_H) * 2u;
        uint32_t bbase = sb + (uint32_t)(STAGES * A_SZ_H + stage * B_SZ_H) * 2u;
        #pragma unroll
        for (int i = 0; i < 4; i++) {
            int c = tid + i * 128;
            int r = c >> 2, j = c & 3;
            const __half* src;
            int vb = 16;
            if (INDIRECT) {
                int tok = tokmap[r];
                if (tok < 0) { vb = 0; src = A; }
                else src = A + (long long)tok * Kd + kk + j * 8;
            } else {
                src = Aptr + (long long)r * Kd + kk + j * 8;
                if (GROUPED && r >= rows) { vb = 0; src = Aptr; }
            }
            cp_async16(abase + (uint32_t)(r * A_STRIDE_H + j * 8) * 2u, src, vb);
        }
        #pragma unroll
        for (int i = 0; i < 4; i++) {
            int c = tid + i * 128;
            int r = c >> 4, j = c & 15;
            int seg = j >> 2, inner = (j & 3) * 8;
            const __half* base = (seg & 1) ? Bup : Bgp;
            const __half* src = base + (long long)(kk + r) * Nh + (seg >> 1) * 32 + inner;
            cp_async16(bbase + (uint32_t)(r * B_STRIDE_H + j * 8) * 2u, src, 16);
        }
        asm volatile("cp.async.commit_group;" ::: "memory");
    };

    issue(0, 0);
    issue(1, 1);
    issue(2, 2);
    issue(3, 3);

    int lhalf = lane & 15, lsel8 = (lane >> 4) << 3;
    int stage = 0, wstage = 4;
    for (int it = 0; it < T; it++) {
        asm volatile("cp.async.wait_group 3;" ::: "memory");
        __syncthreads();
        if (it + 4 < T) issue(wstage, it + 4);

        uint32_t abase = sb + (uint32_t)(stage * A_SZ_H) * 2u;
        uint32_t bbase = sb + (uint32_t)(STAGES * A_SZ_H + stage * B_SZ_H) * 2u;

        #pragma unroll
        for (int ks = 0; ks < 2; ks++) {
            int k0 = ks * 16;
            uint32_t af[4][4], bf[4][4];
            #pragma unroll
            for (int mi = 0; mi < 4; mi++)
                ldmatrix_x4(af[mi], abase +
                    (uint32_t)((wmb + mi * 16 + lhalf) * A_STRIDE_H + k0 + lsel8) * 2u);
            #pragma unroll
            for (int nc = 0; nc < 4; nc++)
                ldmatrix_x4_trans(bf[nc], bbase +
                    (uint32_t)((k0 + lhalf) * B_STRIDE_H + wnb + nc * 16 + lsel8) * 2u);
            #pragma unroll
            for (int mi = 0; mi < 4; mi++)
                #pragma unroll
                for (int nc = 0; nc < 4; nc++) {
                    mma_f16(acc[mi][2 * nc + 0], af[mi], &bf[nc][0]);
                    mma_f16(acc[mi][2 * nc + 1], af[mi], &bf[nc][2]);
                }
        }
        if (++stage == STAGES) stage = 0;
        if (++wstage == STAGES) wstage = 0;
    }

    // ---- in-register SwiGLU epilogue ----
    int hbase = h0 + (wnb >> 1);
    #pragma unroll
    for (int mi = 0; mi < 4; mi++) {
        #pragma unroll
        for (int h = 0; h < 2; h++) {
            int rl = wmb + mi * 16 + g + 8 * h;
            if (GROUPED && rl >= rows) continue;
            __half* dst = Hout + (size_t)(row_start + rl) * Nh + hbase;
            #pragma unroll
            for (int ni = 0; ni < 4; ni++) {
                float g0 = acc[mi][ni][2 * h + 0];
                float g1 = acc[mi][ni][2 * h + 1];
                float u0 = acc[mi][ni + 4][2 * h + 0];
                float u1 = acc[mi][ni + 4][2 * h + 1];
                float r0 = g0 / (1.f + expf(-g0)) * u0;
                float r1 = g1 / (1.f + expf(-g1)) * u1;
                *(__half2*)(dst + ni * 8 + 2 * tig) = __floats2half2_rn(r0, r1);
            }
        }
    }
}

// ================= plain fp16 GEMM (down projections) =================
// MODE 1: red.add rows (no scale) into CoutF[row].
// MODE 2: red.add scaled rows into CoutF[rowmap[row]/TOPK].
template <bool GROUPED, int MODE>
__global__ void __launch_bounds__(GEMM_THREADS, 2) mma_gemm(
    const __half* __restrict__ A, const __half* __restrict__ B0,
    float* __restrict__ CoutF,
    int Kd, int N, long long strideB,
    const int* __restrict__ rowmap, const float* __restrict__ rowscale) {
    extern __shared__ __half smem_h[];

    int row_start, rows, e;
    if (GROUPED) {
        if ((int)blockIdx.y >= g_ntiles) return;
        TileDesc td = g_tiles[blockIdx.y];
        e = td.e; row_start = td.row_start; rows = td.rows;
    } else {
        e = 0; row_start = blockIdx.y * 128; rows = 128;
    }
    int n0 = blockIdx.x * 128;
    const __half* Bptr = B0 + (long long)e * strideB + n0;
    const __half* Aptr = A + (long long)row_start * Kd;

    int tid = threadIdx.x;
    int lane = tid & 31, wid = tid >> 5;
    int g = lane >> 2, tig = lane & 3;
    int wmb = (wid >> 1) * 64;
    int wnb = (wid & 1) * 64;

    uint32_t sb = (uint32_t)__cvta_generic_to_shared(smem_h);

    float acc[4][8][4];
    #pragma unroll
    for (int mi = 0; mi < 4; mi++)
        #pragma unroll
        for (int ni = 0; ni < 8; ni++)
            #pragma unroll
            for (int q = 0; q < 4; q++) acc[mi][ni][q] = 0.f;

    const int T = Kd >> 5;

    auto issue = [&](int stage, int it) {
        int kk = it * 32;
        uint32_t abase = sb + (uint32_t)(stage * A_SZ_H) * 2u;
        uint32_t bbase = sb + (uint32_t)(STAGES * A_SZ_H + stage * B_SZ_H) * 2u;
        #pragma unroll
        for (int i = 0; i < 4; i++) {
            int c = tid + i * 128;
            int r = c >> 2, j = c & 3;
            const __half* src = Aptr + (long long)r * Kd + kk + j * 8;
            int vb = 16;
            if (GROUPED && r >= rows) { vb = 0; src = Aptr; }
            cp_async16(abase + (uint32_t)(r * A_STRIDE_H + j * 8) * 2u, src, vb);
        }
        #pragma unroll
        for (int i = 0; i < 4; i++) {
            int c = tid + i * 128;
            int r = c >> 4, j = c & 15;
            cp_async16(bbase + (uint32_t)(r * B_STRIDE_H + j * 8) * 2u,
                       Bptr + (long long)(kk + r) * N + j * 8, 16);
        }
        asm volatile("cp.async.commit_group;" ::: "memory");
    };

    issue(0, 0);
    issue(1, 1);
    issue(2, 2);
    issue(3, 3);

    int lhalf = lane & 15, lsel8 = (lane >> 4) << 3;
    int stage = 0, wstage = 4;
    for (int it = 0; it < T; it++) {
        asm volatile("cp.async.wait_group 3;" ::: "memory");
        __syncthreads();
        if (it + 4 < T) issue(wstage, it + 4);

        uint32_t abase = sb + (uint32_t)(stage * A_SZ_H) * 2u;
        uint32_t bbase = sb + (uint32_t)(STAGES * A_SZ_H + stage * B_SZ_H) * 2u;

        #pragma unroll
        for (int ks = 0; ks < 2; ks++) {
            int k0 = ks * 16;
            uint32_t af[4][4], bf[4][4];
            #pragma unroll
            for (int mi = 0; mi < 4; mi++)
                ldmatrix_x4(af[mi], abase +
                    (uint32_t)((wmb + mi * 16 + lhalf) * A_STRIDE_H + k0 + lsel8) * 2u);
            #pragma unroll
            for (int nc = 0; nc < 4; nc++)
                ldmatrix_x4_trans(bf[nc], bbase +
                    (uint32_t)((k0 + lhalf) * B_STRIDE_H + wnb + nc * 16 + lsel8) * 2u);
            #pragma unroll
            for (int mi = 0; mi < 4; mi++)
                #pragma unroll
                for (int nc = 0; nc < 4; nc++) {
                    mma_f16(acc[mi][2 * nc + 0], af[mi], &bf[nc][0]);
                    mma_f16(acc[mi][2 * nc + 1], af[mi], &bf[nc][2]);
                }
        }
        if (++stage == STAGES) stage = 0;
        if (++wstage == STAGES) wstage = 0;
    }

    #pragma unroll
    for (int mi = 0; mi < 4; mi++) {
        #pragma unroll
        for (int h = 0; h < 2; h++) {
            int rl = wmb + mi * 16 + g + 8 * h;
            if (GROUPED && rl >= rows) continue;
            if (MODE == 2) {
                int d = rowmap[row_start + rl];
                float scale = rowscale[d];
                float* dst = CoutF + (size_t)(d / TOPK) * N;
                #pragma unroll
                for (int ni = 0; ni < 8; ni++) {
                    int col = n0 + wnb + ni * 8 + 2 * tig;
                    red_add_v2(dst + col,
                               acc[mi][ni][2 * h + 0] * scale,
                               acc[mi][ni][2 * h + 1] * scale);
                }
            } else {
                float* dst = CoutF + (size_t)(row_start + rl) * N;
                #pragma unroll
                for (int ni = 0; ni < 8; ni++) {
                    int col = n0 + wnb + ni * 8 + 2 * tig;
                    red_add_v2(dst + col,
                               acc[mi][ni][2 * h + 0],
                               acc[mi][ni][2 * h + 1]);
                }
            }
        }
    }
}

// ---------------- launch ----------------
extern "C" void kernel_launch(void* const* d_in, const int* in_sizes, int n_in,
                              void* d_out, int out_size) {
    const float* x        = (const float*)d_in[0];
    const float* router_w = (const float*)d_in[1];
    const float* e_bias   = (const float*)d_in[2];
    const float* gate_w   = (const float*)d_in[3];
    const float* up_w     = (const float*)d_in[4];
    const float* down_w   = (const float*)d_in[5];
    const float* sh_gate  = (const float*)d_in[6];
    const float* sh_up    = (const float*)d_in[7];
    const float* sh_down  = (const float*)d_in[8];
    float* out = (float*)d_out;

    __half *p_hbuf, *p_sh_h, *p_x_r;
    __half *p_w_gate, *p_w_up, *p_w_down, *p_w_shg, *p_w_shu, *p_w_shd;
    float *p_topk_w, *p_scores;
    int* p_rowmap;
    cudaGetSymbolAddress((void**)&p_hbuf,     g_hbuf);
    cudaGetSymbolAddress((void**)&p_sh_h,     g_sh_h);
    cudaGetSymbolAddress((void**)&p_topk_w,   g_topk_w);
    cudaGetSymbolAddress((void**)&p_rowmap,   g_rowmap);
    cudaGetSymbolAddress((void**)&p_x_r,      g_x_r);
    cudaGetSymbolAddress((void**)&p_scores,   g_scores);
    cudaGetSymbolAddress((void**)&p_w_gate,   g_w_gate);
    cudaGetSymbolAddress((void**)&p_w_up,     g_w_up);
    cudaGetSymbolAddress((void**)&p_w_down,   g_w_down);
    cudaGetSymbolAddress((void**)&p_w_shg,    g_w_shg);
    cudaGetSymbolAddress((void**)&p_w_shu,    g_w_shu);
    cudaGetSymbolAddress((void**)&p_w_shd,    g_w_shd);

    cudaFuncSetAttribute((const void*)gu_gemm<false, false>,
                         cudaFuncAttributeMaxDynamicSharedMemorySize, GEMM_SMEM_BYTES);
    cudaFuncSetAttribute((const void*)gu_gemm<true, true>,
                         cudaFuncAttributeMaxDynamicSharedMemorySize, GEMM_SMEM_BYTES);
    cudaFuncSetAttribute((const void*)mma_gemm<false, 1>,
                         cudaFuncAttributeMaxDynamicSharedMemorySize, GEMM_SMEM_BYTES);
    cudaFuncSetAttribute((const void*)mma_gemm<true, 2>,
                         cudaFuncAttributeMaxDynamicSharedMemorySize, GEMM_SMEM_BYTES);
    int score_smem = SCORE_TOK * XS_STRIDE * 4;
    cudaFuncSetAttribute((const void*)score_kernel,
                         cudaFuncAttributeMaxDynamicSharedMemorySize, score_smem);

    // one-time side stream + events (created OUTSIDE graph capture)
    static cudaStream_t s_side = nullptr;
    static cudaEvent_t s_fork, s_xr, s_join;
    if (!s_side) {
        cudaStreamCreateWithFlags(&s_side, cudaStreamNonBlocking);
        cudaEventCreateWithFlags(&s_fork, cudaEventDisableTiming);
        cudaEventCreateWithFlags(&s_xr,   cudaEventDisableTiming);
        cudaEventCreateWithFlags(&s_join, cudaEventDisableTiming);
    }

    long long n4;

    // ---- zero the output FIRST (both down GEMMs reduce into it) ----
    cudaMemsetAsync(out, 0, (size_t)S_TOK * CDIM * sizeof(float), 0);

    // ---- fork (side inherits the memset dependency) ----
    cudaEventRecord(s_fork, 0);
    cudaStreamWaitEvent(s_side, s_fork, 0);

    // ===== SIDE STREAM: routing + expert weights + routed GEMMs =====
    score_kernel<<<dim3(EXP / 16, S_TOK / SCORE_TOK), 256, score_smem, s_side>>>(
        x, router_w, p_scores);
    select_kernel<<<SEL_NBLK, SEL_BLK, 0, s_side>>>(p_scores, e_bias);
    {
        long long total = 3LL << EW_N4_SHIFT;
        half_copy3<<<(unsigned)(total / 256), 256, 0, s_side>>>(
            (const float4*)gate_w, (const float4*)up_w, (const float4*)down_w,
            (__half2*)p_w_gate, (__half2*)p_w_up, (__half2*)p_w_down);
    }
    setup_kernel<<<1, 64, 0, s_side>>>();
    assign_kernel<<<NROWS / 256, 256, 0, s_side>>>();

    // ===== MAIN STREAM: x_r first (unblocks side GEMM earliest) =====
    n4 = (long long)S_TOK * CDIM / 4;
    half_copy<<<(unsigned)((n4 + 255) / 256), 256>>>((const float4*)x, (__half2*)p_x_r, n4);
    cudaEventRecord(s_xr, 0);
    n4 = (long long)CDIM * HSHARED / 4;
    half_copy<<<(unsigned)((n4 + 255) / 256), 256>>>((const float4*)sh_gate, (__half2*)p_w_shg, n4);
    half_copy<<<(unsigned)((n4 + 255) / 256), 256>>>((const float4*)sh_up,   (__half2*)p_w_shu, n4);
    half_copy<<<(unsigned)((n4 + 255) / 256), 256>>>((const float4*)sh_down, (__half2*)p_w_shd, n4);

    // side: routed gu GEMM + routed down (fully independent of shared chain)
    cudaStreamWaitEvent(s_side, s_xr, 0);
    gu_gemm<true, true><<<dim3(HDIM / 64, MAX_TILES), GEMM_THREADS, GEMM_SMEM_BYTES, s_side>>>(
        p_x_r, p_w_gate, p_w_up, p_hbuf, CDIM, HDIM, (long long)CDIM * HDIM);
    mma_gemm<true, 2><<<dim3(CDIM / 128, MAX_TILES), GEMM_THREADS, GEMM_SMEM_BYTES, s_side>>>(
        p_hbuf, p_w_down, out, HDIM, CDIM, (long long)HDIM * CDIM,
        p_rowmap, p_topk_w);
    cudaEventRecord(s_join, s_side);

    // main: shared expert GEMMs (shared down reduces into out)
    gu_gemm<false, false><<<dim3(HSHARED / 64, S_TOK / 128), GEMM_THREADS, GEMM_SMEM_BYTES>>>(
        p_x_r, p_w_shg, p_w_shu, p_sh_h, CDIM, HSHARED, 0);
    mma_gemm<false, 1><<<dim3(CDIM / 128, S_TOK / 128), GEMM_THREADS, GEMM_SMEM_BYTES>>>(
        p_sh_h, p_w_shd, out, HSHARED, CDIM, 0, nullptr, nullptr);

    // ---- join side back into the origin stream ----
    cudaStreamWaitEvent(0, s_join, 0);
}

// round 16
// speedup vs baseline: 1.0104x; 1.0104x over previous
#include <cuda_runtime.h>
#include <cuda_fp16.h>
#include <math.h>
#include <stdint.h>

// ---------------- problem constants ----------------
#define S_TOK   4096
#define CDIM    1024
#define EXP     64
#define TOPK    8
#define NGRP    8
#define EPG     8
#define TGRP    4
#define HDIM    512
#define HSHARED 2048
#define NROWS   (S_TOK * TOPK)   // 32768
#define MAX_TILES 320
#define SEL_BLK 128
#define SEL_NBLK (S_TOK / SEL_BLK)   // 32

// ---------------- scratch (static device globals) ----------------
struct TileDesc { int e; int row_start; int rows; };

__device__ int      g_cnt_part[SEL_NBLK * EXP];
__device__ int      g_cursor[EXP];
__device__ TileDesc g_tiles[MAX_TILES];
__device__ int      g_ntiles;
__device__ int      g_rowmap[NROWS];
__device__ int      g_topk_idx[NROWS];
__device__ float    g_topk_w[NROWS];
__device__ float    g_scores[(size_t)S_TOK * EXP];

__device__ __half   g_hbuf[(size_t)NROWS * HDIM];       // routed h (post-swiglu)
__device__ __half   g_sh_h[(size_t)S_TOK * HSHARED];    // shared h (post-swiglu)
__device__ __half   g_x_r[(size_t)S_TOK * CDIM];

// fp16 weight copies (native [K][N] layouts preserved)
__device__ __half   g_w_gate[(size_t)EXP * CDIM * HDIM];
__device__ __half   g_w_up[(size_t)EXP * CDIM * HDIM];
__device__ __half   g_w_down[(size_t)EXP * HDIM * CDIM];
__device__ __half   g_w_shg[(size_t)CDIM * HSHARED];
__device__ __half   g_w_shu[(size_t)CDIM * HSHARED];
__device__ __half   g_w_shd[(size_t)HSHARED * CDIM];

// ---------------- helpers ----------------
__device__ __forceinline__ void mma_f16(float* c, const uint32_t* a, const uint32_t* b) {
    asm volatile(
        "mma.sync.aligned.m16n8k16.row.col.f32.f16.f16.f32 "
        "{%0,%1,%2,%3}, {%4,%5,%6,%7}, {%8,%9}, {%0,%1,%2,%3};"
        : "+f"(c[0]), "+f"(c[1]), "+f"(c[2]), "+f"(c[3])
        : "r"(a[0]), "r"(a[1]), "r"(a[2]), "r"(a[3]), "r"(b[0]), "r"(b[1]));
}
__device__ __forceinline__ void ldmatrix_x4(uint32_t* r, uint32_t addr) {
    asm volatile("ldmatrix.sync.aligned.m8n8.x4.shared.b16 {%0,%1,%2,%3}, [%4];"
                 : "=r"(r[0]), "=r"(r[1]), "=r"(r[2]), "=r"(r[3]) : "r"(addr));
}
__device__ __forceinline__ void ldmatrix_x4_trans(uint32_t* r, uint32_t addr) {
    asm volatile("ldmatrix.sync.aligned.m8n8.x4.trans.shared.b16 {%0,%1,%2,%3}, [%4];"
                 : "=r"(r[0]), "=r"(r[1]), "=r"(r[2]), "=r"(r[3]) : "r"(addr));
}
__device__ __forceinline__ void cp_async16(uint32_t dst, const void* src, int srcbytes) {
    asm volatile("cp.async.cg.shared.global [%0], [%1], 16, %2;"
                 :: "r"(dst), "l"(src), "r"(srcbytes));
}
__device__ __forceinline__ void red_add_v2(float* ptr, float a, float b) {
    asm volatile("red.global.add.v2.f32 [%0], {%1, %2};"
                 :: "l"(ptr), "f"(a), "f"(b) : "memory");
}

// ---------------- prep: f32 -> f16 convert copies ----------------
__global__ void half_copy(const float4* __restrict__ src, __half2* __restrict__ dst,
                          long long n4) {
    long long i = (long long)blockIdx.x * blockDim.x + threadIdx.x;
    if (i >= n4) return;
    float4 v = src[i];
    dst[i * 2 + 0] = __floats2half2_rn(v.x, v.y);
    dst[i * 2 + 1] = __floats2half2_rn(v.z, v.w);
}

// merged convert of 3 equally-sized tensors (size = 1 << SHIFT float4s each)
template <int SHIFT>
__global__ void half_copy3(const float4* __restrict__ s0, const float4* __restrict__ s1,
                           const float4* __restrict__ s2,
                           __half2* __restrict__ d0, __half2* __restrict__ d1,
                           __half2* __restrict__ d2) {
    long long i = (long long)blockIdx.x * blockDim.x + threadIdx.x;
    int sel = (int)(i >> SHIFT);
    long long idx = i & ((1LL << SHIFT) - 1);
    const float4* s = (sel == 0) ? s0 : (sel == 1) ? s1 : s2;
    __half2* d = (sel == 0) ? d0 : (sel == 1) ? d1 : d2;
    float4 v = s[idx];
    d[idx * 2 + 0] = __floats2half2_rn(v.x, v.y);
    d[idx * 2 + 1] = __floats2half2_rn(v.z, v.w);
}

// ---------------- routing ----------------
#define SCORE_TOK 16
#define XS_STRIDE 1028
__global__ void __launch_bounds__(256) score_kernel(
    const float* __restrict__ x, const float* __restrict__ rw,
    float* __restrict__ scores) {
    extern __shared__ float xs[];   // [SCORE_TOK][XS_STRIDE]
    int t0 = blockIdx.y * SCORE_TOK;
    int tid = threadIdx.x, lane = tid & 31, wid = tid >> 5;

    for (int idx = tid; idx < SCORE_TOK * 256; idx += 256) {
        int t = idx >> 8, j = idx & 255;
        *(float4*)&xs[t * XS_STRIDE + j * 4] =
            *(const float4*)(x + (size_t)(t0 + t) * CDIM + j * 4);
    }
    __syncthreads();

    int e0 = blockIdx.x * 16 + wid * 2;
    const float* w0 = rw + (size_t)e0 * CDIM;
    const float* w1 = rw + (size_t)(e0 + 1) * CDIM;
    float acc0[SCORE_TOK], acc1[SCORE_TOK];
    #pragma unroll
    for (int t = 0; t < SCORE_TOK; t++) { acc0[t] = 0.f; acc1[t] = 0.f; }

    #pragma unroll
    for (int i = 0; i < 8; i++) {
        int c = lane * 4 + i * 128;
        float4 a = *(const float4*)(w0 + c);
        float4 b = *(const float4*)(w1 + c);
        #pragma unroll
        for (int t = 0; t < SCORE_TOK; t++) {
            float4 xv = *(const float4*)&xs[t * XS_STRIDE + c];
            acc0[t] += a.x * xv.x + a.y * xv.y + a.z * xv.z + a.w * xv.w;
            acc1[t] += b.x * xv.x + b.y * xv.y + b.z * xv.z + b.w * xv.w;
        }
    }
    #pragma unroll
    for (int t = 0; t < SCORE_TOK; t++) {
        float s0 = acc0[t], s1 = acc1[t];
        #pragma unroll
        for (int o = 16; o > 0; o >>= 1) {
            s0 += __shfl_xor_sync(0xffffffffu, s0, o);
            s1 += __shfl_xor_sync(0xffffffffu, s1, o);
        }
        if (lane == 0) {
            scores[(size_t)(t0 + t) * EXP + e0]     = 1.f / (1.f + expf(-s0));
            scores[(size_t)(t0 + t) * EXP + e0 + 1] = 1.f / (1.f + expf(-s1));
        }
    }
}

__global__ void __launch_bounds__(SEL_BLK) select_kernel(
    const float* __restrict__ scores, const float* __restrict__ ebias) {
    __shared__ float sbs[SEL_BLK * 65];
    __shared__ float eb[EXP];
    __shared__ int cnt[EXP];
    int tid = threadIdx.x;
    if (tid < EXP) { cnt[tid] = 0; eb[tid] = ebias[tid]; }
    __syncthreads();

    int t = blockIdx.x * SEL_BLK + tid;
    float* sb = &sbs[tid * 65];
    const float* srow = scores + (size_t)t * EXP;
    for (int e = 0; e < EXP; e++) sb[e] = srow[e] + eb[e];

    float grp[NGRP];
    for (int g = 0; g < NGRP; g++) {
        float m1 = -1e30f, m2 = -1e30f;
        for (int j = 0; j < EPG; j++) {
            float v = sb[g * EPG + j];
            if (v > m1) { m2 = m1; m1 = v; }
            else if (v > m2) m2 = v;
        }
        grp[g] = m1 + m2;
    }
    bool gsel[NGRP] = {};
    for (int it = 0; it < TGRP; it++) {
        float best = -1e30f; int bi = 0;
        for (int g = 0; g < NGRP; g++)
            if (!gsel[g] && grp[g] > best) { best = grp[g]; bi = g; }
        gsel[bi] = true;
    }
    bool eused[EXP] = {};
    int idx[TOPK]; float wv[TOPK]; float wsum = 0.f;
    for (int it = 0; it < TOPK; it++) {
        float best = -1e30f; int bi = 0;
        for (int e = 0; e < EXP; e++)
            if (gsel[e / EPG] && !eused[e] && sb[e] > best) { best = sb[e]; bi = e; }
        eused[bi] = true; idx[it] = bi;
        float s = srow[bi];
        wv[it] = s; wsum += s;
    }
    float inv = 1.f / (wsum + 1e-20f);
    for (int it = 0; it < TOPK; it++) {
        g_topk_idx[t * TOPK + it] = idx[it];
        g_topk_w[t * TOPK + it]   = wv[it] * inv;
        atomicAdd(&cnt[idx[it]], 1);
    }
    __syncthreads();
    if (tid < EXP) g_cnt_part[blockIdx.x * EXP + tid] = cnt[tid];
}

__global__ void setup_kernel() {
    __shared__ int s[EXP];
    __shared__ int s2[EXP];
    int t = threadIdx.x;
    int c = 0;
    for (int b = 0; b < SEL_NBLK; b++) c += g_cnt_part[b * EXP + t];
    int nt_e = (c + 127) >> 7;
    s[t] = c; s2[t] = nt_e;
    __syncthreads();
    for (int off = 1; off < EXP; off <<= 1) {
        int v = (t >= off) ? s[t - off] : 0;
        int v2 = (t >= off) ? s2[t - off] : 0;
        __syncthreads();
        s[t] += v; s2[t] += v2;
        __syncthreads();
    }
    int off_e = s[t] - c;
    int toff_e = s2[t] - nt_e;
    g_cursor[t] = off_e;
    if (t == EXP - 1) g_ntiles = s2[t];
    for (int r = 0, k = 0; r < c; r += 128, k++) {
        g_tiles[toff_e + k].e = t;
        g_tiles[toff_e + k].row_start = off_e + r;
        g_tiles[toff_e + k].rows = min(128, c - r);
    }
}

__global__ void assign_kernel() {
    int d = blockIdx.x * blockDim.x + threadIdx.x;
    if (d >= NROWS) return;
    int e = g_topk_idx[d];
    int pos = atomicAdd(&g_cursor[e], 1);
    g_rowmap[pos] = d;
}

// ---------------- GEMM tiling constants ----------------
#define GEMM_THREADS 128
#define STAGES 5
#define A_STRIDE_H 40
#define B_STRIDE_H 136
#define A_SZ_H (128 * A_STRIDE_H)           // 5120 halfs
#define B_SZ_H (32 * B_STRIDE_H)            // 4352 halfs
#define PIPE_H (STAGES * (A_SZ_H + B_SZ_H)) // 47360 halfs = 94720 B
#define GEMM_SMEM_BYTES (PIPE_H * 2 + 512)  // + tokmap

// ================= fused gate|up GEMM + in-register SwiGLU =================
template <bool GROUPED, bool INDIRECT>
__global__ void __launch_bounds__(GEMM_THREADS, 2) gu_gemm(
    const __half* __restrict__ A, const __half* __restrict__ Bg,
    const __half* __restrict__ Bu, __half* __restrict__ Hout,
    int Kd, int Nh, long long strideB) {
    extern __shared__ __half smem_h[];
    int* tokmap = (int*)(smem_h + PIPE_H);

    int row_start, rows, e;
    if (GROUPED) {
        if ((int)blockIdx.y >= g_ntiles) return;
        TileDesc td = g_tiles[blockIdx.y];
        e = td.e; row_start = td.row_start; rows = td.rows;
    } else {
        e = 0; row_start = blockIdx.y * 128; rows = 128;
    }
    int h0 = blockIdx.x * 64;
    const __half* Bgp = Bg + (long long)e * strideB + h0;
    const __half* Bup = Bu + (long long)e * strideB + h0;
    const __half* Aptr = A + (long long)row_start * Kd;

    int tid = threadIdx.x;
    int lane = tid & 31, wid = tid >> 5;
    int g = lane >> 2, tig = lane & 3;
    int wmb = (wid >> 1) * 64;
    int wnb = (wid & 1) * 64;

    if (INDIRECT) {
        tokmap[tid] = (tid < rows) ? (g_rowmap[row_start + tid] / TOPK) : -1;
        __syncthreads();
    }

    uint32_t sb = (uint32_t)__cvta_generic_to_shared(smem_h);

    float acc[4][8][4];
    #pragma unroll
    for (int mi = 0; mi < 4; mi++)
        #pragma unroll
        for (int ni = 0; ni < 8; ni++)
            #pragma unroll
            for (int q = 0; q < 4; q++) acc[mi][ni][q] = 0.f;

    const int T = Kd >> 5;

    auto issue = [&](int stage, int it) {
        int kk = it * 32;
        uint32_t abase = sb + (uint32_t)(stage * A_SZ_H) * 2u;
        uint32_t bbase = sb + (uint32_t)(STAGES * A_SZ_H + stage * B_SZ_H) * 2u;
        #pragma unroll
        for (int i = 0; i < 4; i++) {
            int c = tid + i * 128;
            int r = c >> 2, j = c & 3;
            const __half* src;
            int vb = 16;
            if (INDIRECT) {
                int tok = tokmap[r];
                if (tok < 0) { vb = 0; src = A; }
                else src = A + (long long)tok * Kd + kk + j * 8;
            } else {
                src = Aptr + (long long)r * Kd + kk + j * 8;
                if (GROUPED && r >= rows) { vb = 0; src = Aptr; }
            }
            cp_async16(abase + (uint32_t)(r * A_STRIDE_H + j * 8) * 2u, src, vb);
        }
        #pragma unroll
        for (int i = 0; i < 4; i++) {
            int c = tid + i * 128;
            int r = c >> 4, j = c & 15;
            int seg = j >> 2, inner = (j & 3) * 8;
            const __half* base = (seg & 1) ? Bup : Bgp;
            const __half* src = base + (long long)(kk + r) * Nh + (seg >> 1) * 32 + inner;
            cp_async16(bbase + (uint32_t)(r * B_STRIDE_H + j * 8) * 2u, src, 16);
        }
        asm volatile("cp.async.commit_group;" ::: "memory");
    };

    issue(0, 0);
    issue(1, 1);
    issue(2, 2);
    issue(3, 3);

    int lhalf = lane & 15, lsel8 = (lane >> 4) << 3;
    int stage = 0, wstage = 4;
    for (int it = 0; it < T; it++) {
        asm volatile("cp.async.wait_group 3;" ::: "memory");
        __syncthreads();
        if (it + 4 < T) issue(wstage, it + 4);

        uint32_t abase = sb + (uint32_t)(stage * A_SZ_H) * 2u;
        uint32_t bbase = sb + (uint32_t)(STAGES * A_SZ_H + stage * B_SZ_H) * 2u;

        #pragma unroll
        for (int ks = 0; ks < 2; ks++) {
            int k0 = ks * 16;
            uint32_t af[4][4], bf[4][4];
            #pragma unroll
            for (int mi = 0; mi < 4; mi++)
                ldmatrix_x4(af[mi], abase +
                    (uint32_t)((wmb + mi * 16 + lhalf) * A_STRIDE_H + k0 + lsel8) * 2u);
            #pragma unroll
            for (int nc = 0; nc < 4; nc++)
                ldmatrix_x4_trans(bf[nc], bbase +
                    (uint32_t)((k0 + lhalf) * B_STRIDE_H + wnb + nc * 16 + lsel8) * 2u);
            #pragma unroll
            for (int mi = 0; mi < 4; mi++)
                #pragma unroll
                for (int nc = 0; nc < 4; nc++) {
                    mma_f16(acc[mi][2 * nc + 0], af[mi], &bf[nc][0]);
                    mma_f16(acc[mi][2 * nc + 1], af[mi], &bf[nc][2]);
                }
        }
        if (++stage == STAGES) stage = 0;
        if (++wstage == STAGES) wstage = 0;
    }

    // ---- in-register SwiGLU epilogue ----
    int hbase = h0 + (wnb >> 1);
    #pragma unroll
    for (int mi = 0; mi < 4; mi++) {
        #pragma unroll
        for (int h = 0; h < 2; h++) {
            int rl = wmb + mi * 16 + g + 8 * h;
            if (GROUPED && rl >= rows) continue;
            __half* dst = Hout + (size_t)(row_start + rl) * Nh + hbase;
            #pragma unroll
            for (int ni = 0; ni < 4; ni++) {
                float g0 = acc[mi][ni][2 * h + 0];
                float g1 = acc[mi][ni][2 * h + 1];
                float u0 = acc[mi][ni + 4][2 * h + 0];
                float u1 = acc[mi][ni + 4][2 * h + 1];
                float r0 = g0 / (1.f + expf(-g0)) * u0;
                float r1 = g1 / (1.f + expf(-g1)) * u1;
                *(__half2*)(dst + ni * 8 + 2 * tig) = __floats2half2_rn(r0, r1);
            }
        }
    }
}

// ================= plain fp16 GEMM (down projections) =================
// MODE 0: fp32 store. MODE 2: red.v2 scaled rows into CoutF[rowmap[row]/TOPK].
template <bool GROUPED, int MODE>
__global__ void __launch_bounds__(GEMM_THREADS, 2) mma_gemm(
    const __half* __restrict__ A, const __half* __restrict__ B0,
    float* __restrict__ CoutF,
    int Kd, int N, long long strideB,
    const int* __restrict__ rowmap, const float* __restrict__ rowscale) {
    extern __shared__ __half smem_h[];

    int row_start, rows, e;
    if (GROUPED) {
        if ((int)blockIdx.y >= g_ntiles) return;
        TileDesc td = g_tiles[blockIdx.y];
        e = td.e; row_start = td.row_start; rows = td.rows;
    } else {
        e = 0; row_start = blockIdx.y * 128; rows = 128;
    }
    int n0 = blockIdx.x * 128;
    const __half* Bptr = B0 + (long long)e * strideB + n0;
    const __half* Aptr = A + (long long)row_start * Kd;

    int tid = threadIdx.x;
    int lane = tid & 31, wid = tid >> 5;
    int g = lane >> 2, tig = lane & 3;
    int wmb = (wid >> 1) * 64;
    int wnb = (wid & 1) * 64;

    uint32_t sb = (uint32_t)__cvta_generic_to_shared(smem_h);

    float acc[4][8][4];
    #pragma unroll
    for (int mi = 0; mi < 4; mi++)
        #pragma unroll
        for (int ni = 0; ni < 8; ni++)
            #pragma unroll
            for (int q = 0; q < 4; q++) acc[mi][ni][q] = 0.f;

    const int T = Kd >> 5;

    auto issue = [&](int stage, int it) {
        int kk = it * 32;
        uint32_t abase = sb + (uint32_t)(stage * A_SZ_H) * 2u;
        uint32_t bbase = sb + (uint32_t)(STAGES * A_SZ_H + stage * B_SZ_H) * 2u;
        #pragma unroll
        for (int i = 0; i < 4; i++) {
            int c = tid + i * 128;
            int r = c >> 2, j = c & 3;
            const __half* src = Aptr + (long long)r * Kd + kk + j * 8;
            int vb = 16;
            if (GROUPED && r >= rows) { vb = 0; src = Aptr; }
            cp_async16(abase + (uint32_t)(r * A_STRIDE_H + j * 8) * 2u, src, vb);
        }
        #pragma unroll
        for (int i = 0; i < 4; i++) {
            int c = tid + i * 128;
            int r = c >> 4, j = c & 15;
            cp_async16(bbase + (uint32_t)(r * B_STRIDE_H + j * 8) * 2u,
                       Bptr + (long long)(kk + r) * N + j * 8, 16);
        }
        asm volatile("cp.async.commit_group;" ::: "memory");
    };

    issue(0, 0);
    issue(1, 1);
    issue(2, 2);
    issue(3, 3);

    int lhalf = lane & 15, lsel8 = (lane >> 4) << 3;
    int stage = 0, wstage = 4;
    for (int it = 0; it < T; it++) {
        asm volatile("cp.async.wait_group 3;" ::: "memory");
        __syncthreads();
        if (it + 4 < T) issue(wstage, it + 4);

        uint32_t abase = sb + (uint32_t)(stage * A_SZ_H) * 2u;
        uint32_t bbase = sb + (uint32_t)(STAGES * A_SZ_H + stage * B_SZ_H) * 2u;

        #pragma unroll
        for (int ks = 0; ks < 2; ks++) {
            int k0 = ks * 16;
            uint32_t af[4][4], bf[4][4];
            #pragma unroll
            for (int mi = 0; mi < 4; mi++)
                ldmatrix_x4(af[mi], abase +
                    (uint32_t)((wmb + mi * 16 + lhalf) * A_STRIDE_H + k0 + lsel8) * 2u);
            #pragma unroll
            for (int nc = 0; nc < 4; nc++)
                ldmatrix_x4_trans(bf[nc], bbase +
                    (uint32_t)((k0 + lhalf) * B_STRIDE_H + wnb + nc * 16 + lsel8) * 2u);
            #pragma unroll
            for (int mi = 0; mi < 4; mi++)
                #pragma unroll
                for (int nc = 0; nc < 4; nc++) {
                    mma_f16(acc[mi][2 * nc + 0], af[mi], &bf[nc][0]);
                    mma_f16(acc[mi][2 * nc + 1], af[mi], &bf[nc][2]);
                }
        }
        if (++stage == STAGES) stage = 0;
        if (++wstage == STAGES) wstage = 0;
    }

    #pragma unroll
    for (int mi = 0; mi < 4; mi++) {
        #pragma unroll
        for (int h = 0; h < 2; h++) {
            int rl = wmb + mi * 16 + g + 8 * h;
            if (GROUPED && rl >= rows) continue;
            if (MODE == 2) {
                int d = rowmap[row_start + rl];
                float scale = rowscale[d];
                float* dst = CoutF + (size_t)(d / TOPK) * N;
                #pragma unroll
                for (int ni = 0; ni < 8; ni++) {
                    int col = n0 + wnb + ni * 8 + 2 * tig;
                    red_add_v2(dst + col,
                               acc[mi][ni][2 * h + 0] * scale,
                               acc[mi][ni][2 * h + 1] * scale);
                }
            } else {
                float* dst = CoutF + (size_t)(row_start + rl) * N;
                #pragma unroll
                for (int ni = 0; ni < 8; ni++) {
                    int col = n0 + wnb + ni * 8 + 2 * tig;
                    float2 v;
                    v.x = acc[mi][ni][2 * h + 0];
                    v.y = acc[mi][ni][2 * h + 1];
                    *(float2*)(dst + col) = v;
                }
            }
        }
    }
}

// ---------------- launch ----------------
extern "C" void kernel_launch(void* const* d_in, const int* in_sizes, int n_in,
                              void* d_out, int out_size) {
    const float* x        = (const float*)d_in[0];
    const float* router_w = (const float*)d_in[1];
    const float* e_bias   = (const float*)d_in[2];
    const float* gate_w   = (const float*)d_in[3];
    const float* up_w     = (const float*)d_in[4];
    const float* down_w   = (const float*)d_in[5];
    const float* sh_gate  = (const float*)d_in[6];
    const float* sh_up    = (const float*)d_in[7];
    const float* sh_down  = (const float*)d_in[8];
    float* out = (float*)d_out;

    __half *p_hbuf, *p_sh_h, *p_x_r;
    __half *p_w_gate, *p_w_up, *p_w_down, *p_w_shg, *p_w_shu, *p_w_shd;
    float *p_topk_w, *p_scores;
    int* p_rowmap;
    cudaGetSymbolAddress((void**)&p_hbuf,     g_hbuf);
    cudaGetSymbolAddress((void**)&p_sh_h,     g_sh_h);
    cudaGetSymbolAddress((void**)&p_topk_w,   g_topk_w);
    cudaGetSymbolAddress((void**)&p_rowmap,   g_rowmap);
    cudaGetSymbolAddress((void**)&p_x_r,      g_x_r);
    cudaGetSymbolAddress((void**)&p_scores,   g_scores);
    cudaGetSymbolAddress((void**)&p_w_gate,   g_w_gate);
    cudaGetSymbolAddress((void**)&p_w_up,     g_w_up);
    cudaGetSymbolAddress((void**)&p_w_down,   g_w_down);
    cudaGetSymbolAddress((void**)&p_w_shg,    g_w_shg);
    cudaGetSymbolAddress((void**)&p_w_shu,    g_w_shu);
    cudaGetSymbolAddress((void**)&p_w_shd,    g_w_shd);

    cudaFuncSetAttribute((const void*)gu_gemm<false, false>,
                         cudaFuncAttributeMaxDynamicSharedMemorySize, GEMM_SMEM_BYTES);
    cudaFuncSetAttribute((const void*)gu_gemm<true, true>,
                         cudaFuncAttributeMaxDynamicSharedMemorySize, GEMM_SMEM_BYTES);
    cudaFuncSetAttribute((const void*)mma_gemm<false, 0>,
                         cudaFuncAttributeMaxDynamicSharedMemorySize, GEMM_SMEM_BYTES);
    cudaFuncSetAttribute((const void*)mma_gemm<true, 2>,
                         cudaFuncAttributeMaxDynamicSharedMemorySize, GEMM_SMEM_BYTES);
    int score_smem = SCORE_TOK * XS_STRIDE * 4;
    cudaFuncSetAttribute((const void*)score_kernel,
                         cudaFuncAttributeMaxDynamicSharedMemorySize, score_smem);

    // one-time side stream + events (created OUTSIDE graph capture)
    static cudaStream_t s_side = nullptr;
    static cudaEvent_t s_fork, s_xr, s_join;
    if (!s_side) {
        cudaStreamCreateWithFlags(&s_side, cudaStreamNonBlocking);
        cudaEventCreateWithFlags(&s_fork, cudaEventDisableTiming);
        cudaEventCreateWithFlags(&s_xr,   cudaEventDisableTiming);
        cudaEventCreateWithFlags(&s_join, cudaEventDisableTiming);
    }

    long long n4;

    // ---- fork ----
    cudaEventRecord(s_fork, 0);
    cudaStreamWaitEvent(s_side, s_fork, 0);

    // ===== SIDE STREAM: routing + expert weight conversion =====
    score_kernel<<<dim3(EXP / 16, S_TOK / SCORE_TOK), 256, score_smem, s_side>>>(
        x, router_w, p_scores);
    select_kernel<<<SEL_NBLK, SEL_BLK, 0, s_side>>>(p_scores, e_bias);
    {
        long long total = 3LL << 23;   // expert weights: 3 x 2^23 float4
        half_copy3<23><<<(unsigned)(total / 256), 256, 0, s_side>>>(
            (const float4*)gate_w, (const float4*)up_w, (const float4*)down_w,
            (__half2*)p_w_gate, (__half2*)p_w_up, (__half2*)p_w_down);
    }
    setup_kernel<<<1, 64, 0, s_side>>>();
    assign_kernel<<<NROWS / 256, 256, 0, s_side>>>();

    // ===== MAIN STREAM: x_r first (unblocks side GEMM earliest) =====
    n4 = (long long)S_TOK * CDIM / 4;
    half_copy<<<(unsigned)((n4 + 255) / 256), 256>>>((const float4*)x, (__half2*)p_x_r, n4);
    cudaEventRecord(s_xr, 0);
    {
        long long total = 3LL << 19;   // shared weights: 3 x 2^19 float4
        half_copy3<19><<<(unsigned)(total / 256), 256>>>(
            (const float4*)sh_gate, (const float4*)sh_up, (const float4*)sh_down,
            (__half2*)p_w_shg, (__half2*)p_w_shu, (__half2*)p_w_shd);
    }

    // side: routed gu GEMM (needs x_r from main + weights/assign from side)
    cudaStreamWaitEvent(s_side, s_xr, 0);
    gu_gemm<true, true><<<dim3(HDIM / 64, MAX_TILES), GEMM_THREADS, GEMM_SMEM_BYTES, s_side>>>(
        p_x_r, p_w_gate, p_w_up, p_hbuf, CDIM, HDIM, (long long)CDIM * HDIM);
    cudaEventRecord(s_join, s_side);

    // main: shared expert GEMMs (overlap with routed gu on side)
    gu_gemm<false, false><<<dim3(HSHARED / 64, S_TOK / 128), GEMM_THREADS, GEMM_SMEM_BYTES>>>(
        p_x_r, p_w_shg, p_w_shu, p_sh_h, CDIM, HSHARED, 0);
    mma_gemm<false, 0><<<dim3(CDIM / 128, S_TOK / 128), GEMM_THREADS, GEMM_SMEM_BYTES>>>(
        p_sh_h, p_w_shd, out, HSHARED, CDIM, 0, nullptr, nullptr);

    // ---- join: routed down needs hbuf (side) and out written (main) ----
    cudaStreamWaitEvent(0, s_join, 0);
    mma_gemm<true, 2><<<dim3(CDIM / 128, MAX_TILES), GEMM_THREADS, GEMM_SMEM_BYTES>>>(
        p_hbuf, p_w_down, out, HDIM, CDIM, (long long)HDIM * CDIM,
        p_rowmap, p_topk_w);
}